// round 12
// baseline (speedup 1.0000x reference)
#include <cuda_runtime.h>

#define MUL 64
#define ROWS_PER_BLOCK 64
#define THREADS 512
#define INV_SQRT3 0.57735026918962576451f

// smem float layout
//   A    [64 rows][64 u][8]   : 0      .. 32768   (reused as output staging [64][256])
//   Wp   [64 u][64 w][4]      : 32768  .. 49152
//   sc   [64 rows][4]         : 49152  .. 49408   (s2, v2x, v2y, v2z)
//   bias [64]                 : 49408  .. 49472
#define SMEM_FLOATS 49472
#define SMEM_BYTES  (SMEM_FLOATS * 4)

__global__ __launch_bounds__(THREADS, 1)
void o3tp_kernel(const float* __restrict__ in1, const float* __restrict__ in2,
                 const float* __restrict__ Wss, const float* __restrict__ Wvv,
                 const float* __restrict__ Wsv, const float* __restrict__ Wvs,
                 const float* __restrict__ bias, float* __restrict__ out, int n)
{
    extern __shared__ float smem[];
    float* A   = smem;
    float* Wp  = smem + 32768;
    float* sc  = smem + 49152;
    float* bsm = smem + 49408;

    const int tid  = threadIdx.x;
    const int row0 = blockIdx.x * ROWS_PER_BLOCK;

    // --- load per-row scalars (s2, v2) and bias ---
    if (tid < 256) {
        int r  = tid >> 2;
        int gr = min(row0 + r, n - 1);
        sc[tid] = in2[gr * 4 + (tid & 3)];
    }
    if (tid < 64) bsm[tid] = bias[tid];

    // --- load + interleave weights: Wp[u][w] = {Wss, Wvv, Wsv, Wvs} ---
    for (int idx = tid; idx < 4096; idx += THREADS) {
        Wp[idx * 4 + 0] = Wss[idx];
        Wp[idx * 4 + 1] = Wvv[idx];
        Wp[idx * 4 + 2] = Wsv[idx];
        Wp[idx * 4 + 3] = Wvs[idx];
    }
    __syncthreads();   // sc must be visible for A-pack below

    // --- pack per-row inputs: A[r][u] = {s1*s2, vv*inv_sqrt3, s1, v1x, v1y, v1z, -, -} ---
    for (int idx = tid; idx < 64 * 64; idx += THREADS) {
        int r  = idx >> 6;
        int u  = idx & 63;
        int gr = min(row0 + r, n - 1);
        const float* rowp = in1 + (long)gr * 256;
        float s1 = rowp[u];
        float vx = rowp[64 + 3 * u + 0];
        float vy = rowp[64 + 3 * u + 1];
        float vz = rowp[64 + 3 * u + 2];
        float s2  = sc[r * 4 + 0];
        float v2x = sc[r * 4 + 1];
        float v2y = sc[r * 4 + 2];
        float v2z = sc[r * 4 + 3];
        float vvs = (vx * v2x + vy * v2y + vz * v2z) * INV_SQRT3;
        float* ap = A + idx * 8;
        ap[0] = s1 * s2;
        ap[1] = vvs;
        ap[2] = s1;
        ap[3] = vx;
        ap[4] = vy;
        ap[5] = vz;
        ap[6] = 0.f;
        ap[7] = 0.f;
    }
    __syncthreads();

    // --- main u-loop: thread = 4 rows x 2 cols, 5 accumulators each ---
    const int c  = tid & 31;   // cols c, c+32  -> warp lanes cover 32 consecutive cols
    const int rg = tid >> 5;   // row group: rows 4*rg .. 4*rg+3 (uniform per warp -> broadcast A loads)

    float acc[4][2][5];
    #pragma unroll
    for (int r = 0; r < 4; r++)
        #pragma unroll
        for (int j = 0; j < 2; j++)
            #pragma unroll
            for (int k = 0; k < 5; k++) acc[r][j][k] = 0.f;

    const float4* A4 = (const float4*)A;
    const float4* W4 = (const float4*)Wp;

    #pragma unroll 4
    for (int u = 0; u < 64; u++) {
        float4 b0 = W4[u * 64 + c];        // {Wss,Wvv,Wsv,Wvs} for col c
        float4 b1 = W4[u * 64 + c + 32];   // for col c+32
        #pragma unroll
        for (int r = 0; r < 4; r++) {
            int base  = ((rg * 4 + r) * 64 + u) * 2;
            float4 a0 = A4[base];       // s1p, vvs, s1, v1x
            float4 a1 = A4[base + 1];   // v1y, v1z, -, -
            acc[r][0][0] += a0.x * b0.x;
            acc[r][0][0] += a0.y * b0.y;
            acc[r][0][1] += a0.z * b0.z;
            acc[r][0][2] += a0.w * b0.w;
            acc[r][0][3] += a1.x * b0.w;
            acc[r][0][4] += a1.y * b0.w;
            acc[r][1][0] += a0.x * b1.x;
            acc[r][1][0] += a0.y * b1.y;
            acc[r][1][1] += a0.z * b1.z;
            acc[r][1][2] += a0.w * b1.w;
            acc[r][1][3] += a1.x * b1.w;
            acc[r][1][4] += a1.y * b1.w;
        }
    }

    __syncthreads();   // all warps done reading A -> reuse it as output staging

    // --- epilogue: combine and stage into smem [64 rows][256 cols] ---
    float* stile = smem;
    #pragma unroll
    for (int r = 0; r < 4; r++) {
        int lr = rg * 4 + r;
        float s2  = sc[lr * 4 + 0];
        float v2x = sc[lr * 4 + 1];
        float v2y = sc[lr * 4 + 2];
        float v2z = sc[lr * 4 + 3];
        float* o = stile + lr * 256;
        #pragma unroll
        for (int j = 0; j < 2; j++) {
            int w = c + 32 * j;
            o[w] = acc[r][j][0] + bsm[w];
            float sv = acc[r][j][1];
            o[64 + 3 * w + 0] = sv * v2x + acc[r][j][2] * s2;
            o[64 + 3 * w + 1] = sv * v2y + acc[r][j][3] * s2;
            o[64 + 3 * w + 2] = sv * v2z + acc[r][j][4] * s2;
        }
    }
    __syncthreads();

    // --- coalesced float4 store of the whole tile ---
    const float4* st4 = (const float4*)stile;
    float4* out4 = (float4*)(out + (long)row0 * 256);
    int rows_here = min(ROWS_PER_BLOCK, n - row0);
    int nfl4 = rows_here * 64;   // 256 floats/row = 64 float4/row
    for (int idx = tid; idx < nfl4; idx += THREADS)
        out4[idx] = st4[idx];
}

extern "C" void kernel_launch(void* const* d_in, const int* in_sizes, int n_in,
                              void* d_out, int out_size) {
    const float* in1  = (const float*)d_in[0];
    const float* in2  = (const float*)d_in[1];
    const float* Wss  = (const float*)d_in[2];
    const float* Wvv  = (const float*)d_in[3];
    const float* Wsv  = (const float*)d_in[4];
    const float* Wvs  = (const float*)d_in[5];
    const float* bias = (const float*)d_in[6];
    float* out = (float*)d_out;

    int n = in_sizes[0] / 256;   // rows

    cudaFuncSetAttribute(o3tp_kernel, cudaFuncAttributeMaxDynamicSharedMemorySize, SMEM_BYTES);

    int blocks = (n + ROWS_PER_BLOCK - 1) / ROWS_PER_BLOCK;
    o3tp_kernel<<<blocks, THREADS, SMEM_BYTES>>>(in1, in2, Wss, Wvv, Wsv, Wvs, bias, out, n);
}

// round 13
// speedup vs baseline: 1.0036x; 1.0036x over previous
#include <cuda_runtime.h>

#define MUL 64
#define ROWS_PER_BLOCK 64
#define THREADS 512
#define INV_SQRT3 0.57735026918962576451f

// smem float layout
//   A    [64 rows][64 u][8]   : 0      .. 32768   (reused as output staging [64][256])
//   Wp   [64 u][64 w][4]      : 32768  .. 49152
//   sc   [64 rows][4]         : 49152  .. 49408   (s2, v2x, v2y, v2z)
//   bias [64]                 : 49408  .. 49472
#define SMEM_FLOATS 49472
#define SMEM_BYTES  (SMEM_FLOATS * 4)

__global__ __launch_bounds__(THREADS, 1)
void o3tp_kernel(const float* __restrict__ in1, const float* __restrict__ in2,
                 const float* __restrict__ Wss, const float* __restrict__ Wvv,
                 const float* __restrict__ Wsv, const float* __restrict__ Wvs,
                 const float* __restrict__ bias, float* __restrict__ out, int n)
{
    extern __shared__ float smem[];
    float* A   = smem;
    float* Wp  = smem + 32768;
    float* sc  = smem + 49152;
    float* bsm = smem + 49408;

    const int tid  = threadIdx.x;
    const int row0 = blockIdx.x * ROWS_PER_BLOCK;

    // --- load per-row scalars (s2, v2) and bias ---
    if (tid < 256) {
        int r  = tid >> 2;
        int gr = min(row0 + r, n - 1);
        sc[tid] = in2[gr * 4 + (tid & 3)];
    }
    if (tid < 64) bsm[tid] = bias[tid];

    // --- load + interleave weights: Wp[u][w] = {Wss, Wvv, Wsv, Wvs} ---
    for (int idx = tid; idx < 4096; idx += THREADS) {
        Wp[idx * 4 + 0] = Wss[idx];
        Wp[idx * 4 + 1] = Wvv[idx];
        Wp[idx * 4 + 2] = Wsv[idx];
        Wp[idx * 4 + 3] = Wvs[idx];
    }
    __syncthreads();   // sc must be visible for A-pack below

    // --- pack per-row inputs: A[r][u] = {s1*s2, vv*inv_sqrt3, s1, v1x, v1y, v1z, -, -} ---
    for (int idx = tid; idx < 64 * 64; idx += THREADS) {
        int r  = idx >> 6;
        int u  = idx & 63;
        int gr = min(row0 + r, n - 1);
        const float* rowp = in1 + (long)gr * 256;
        float s1 = rowp[u];
        float vx = rowp[64 + 3 * u + 0];
        float vy = rowp[64 + 3 * u + 1];
        float vz = rowp[64 + 3 * u + 2];
        float s2  = sc[r * 4 + 0];
        float v2x = sc[r * 4 + 1];
        float v2y = sc[r * 4 + 2];
        float v2z = sc[r * 4 + 3];
        float vvs = (vx * v2x + vy * v2y + vz * v2z) * INV_SQRT3;
        float* ap = A + idx * 8;
        ap[0] = s1 * s2;
        ap[1] = vvs;
        ap[2] = s1;
        ap[3] = vx;
        ap[4] = vy;
        ap[5] = vz;
        ap[6] = 0.f;
        ap[7] = 0.f;
    }
    __syncthreads();

    // --- main u-loop: thread = 4 rows x 2 cols, 5 accumulators each ---
    const int c  = tid & 31;   // cols c, c+32  -> warp lanes cover 32 consecutive cols
    const int rg = tid >> 5;   // row group: rows 4*rg .. 4*rg+3 (uniform per warp -> broadcast A loads)

    float acc[4][2][5];
    #pragma unroll
    for (int r = 0; r < 4; r++)
        #pragma unroll
        for (int j = 0; j < 2; j++)
            #pragma unroll
            for (int k = 0; k < 5; k++) acc[r][j][k] = 0.f;

    const float4* A4 = (const float4*)A;
    const float4* W4 = (const float4*)Wp;

    #pragma unroll 4
    for (int u = 0; u < 64; u++) {
        float4 b0 = W4[u * 64 + c];        // {Wss,Wvv,Wsv,Wvs} for col c
        float4 b1 = W4[u * 64 + c + 32];   // for col c+32
        #pragma unroll
        for (int r = 0; r < 4; r++) {
            int base  = ((rg * 4 + r) * 64 + u) * 2;
            float4 a0 = A4[base];       // s1p, vvs, s1, v1x
            float4 a1 = A4[base + 1];   // v1y, v1z, -, -
            acc[r][0][0] += a0.x * b0.x;
            acc[r][0][0] += a0.y * b0.y;
            acc[r][0][1] += a0.z * b0.z;
            acc[r][0][2] += a0.w * b0.w;
            acc[r][0][3] += a1.x * b0.w;
            acc[r][0][4] += a1.y * b0.w;
            acc[r][1][0] += a0.x * b1.x;
            acc[r][1][0] += a0.y * b1.y;
            acc[r][1][1] += a0.z * b1.z;
            acc[r][1][2] += a0.w * b1.w;
            acc[r][1][3] += a1.x * b1.w;
            acc[r][1][4] += a1.y * b1.w;
        }
    }

    __syncthreads();   // all warps done reading A -> reuse it as output staging

    // --- epilogue: combine and stage into smem [64 rows][256 cols] ---
    float* stile = smem;
    #pragma unroll
    for (int r = 0; r < 4; r++) {
        int lr = rg * 4 + r;
        float s2  = sc[lr * 4 + 0];
        float v2x = sc[lr * 4 + 1];
        float v2y = sc[lr * 4 + 2];
        float v2z = sc[lr * 4 + 3];
        float* o = stile + lr * 256;
        #pragma unroll
        for (int j = 0; j < 2; j++) {
            int w = c + 32 * j;
            o[w] = acc[r][j][0] + bsm[w];
            float sv = acc[r][j][1];
            o[64 + 3 * w + 0] = sv * v2x + acc[r][j][2] * s2;
            o[64 + 3 * w + 1] = sv * v2y + acc[r][j][3] * s2;
            o[64 + 3 * w + 2] = sv * v2z + acc[r][j][4] * s2;
        }
    }
    __syncthreads();

    // --- coalesced float4 store of the whole tile ---
    const float4* st4 = (const float4*)stile;
    float4* out4 = (float4*)(out + (long)row0 * 256);
    int rows_here = min(ROWS_PER_BLOCK, n - row0);
    int nfl4 = rows_here * 64;   // 256 floats/row = 64 float4/row
    for (int idx = tid; idx < nfl4; idx += THREADS)
        out4[idx] = st4[idx];
}

extern "C" void kernel_launch(void* const* d_in, const int* in_sizes, int n_in,
                              void* d_out, int out_size) {
    const float* in1  = (const float*)d_in[0];
    const float* in2  = (const float*)d_in[1];
    const float* Wss  = (const float*)d_in[2];
    const float* Wvv  = (const float*)d_in[3];
    const float* Wsv  = (const float*)d_in[4];
    const float* Wvs  = (const float*)d_in[5];
    const float* bias = (const float*)d_in[6];
    float* out = (float*)d_out;

    int n = in_sizes[0] / 256;   // rows

    cudaFuncSetAttribute(o3tp_kernel, cudaFuncAttributeMaxDynamicSharedMemorySize, SMEM_BYTES);

    int blocks = (n + ROWS_PER_BLOCK - 1) / ROWS_PER_BLOCK;
    o3tp_kernel<<<blocks, THREADS, SMEM_BYTES>>>(in1, in2, Wss, Wvv, Wsv, Wvs, bias, out, n);
}

// round 14
// speedup vs baseline: 1.0166x; 1.0130x over previous
#include <cuda_runtime.h>

#define MUL 64
#define ROWS_PER_BLOCK 64
#define THREADS 512
#define INV_SQRT3 0.57735026918962576451f

// smem float layout
//   A    [64 rows][64 u][8]   : 0      .. 32768   (reused as output staging [64][256])
//   Wp   [64 u][64 w][4]      : 32768  .. 49152
//   sc   [64 rows][4]         : 49152  .. 49408   (s2, v2x, v2y, v2z)
//   bias [64]                 : 49408  .. 49472
#define SMEM_FLOATS 49472
#define SMEM_BYTES  (SMEM_FLOATS * 4)

__global__ __launch_bounds__(THREADS, 1)
void o3tp_kernel(const float* __restrict__ in1, const float* __restrict__ in2,
                 const float* __restrict__ Wss, const float* __restrict__ Wvv,
                 const float* __restrict__ Wsv, const float* __restrict__ Wvs,
                 const float* __restrict__ bias, float* __restrict__ out, int n)
{
    extern __shared__ float smem[];
    float* A   = smem;
    float* Wp  = smem + 32768;
    float* sc  = smem + 49152;
    float* bsm = smem + 49408;

    const int tid  = threadIdx.x;
    const int row0 = blockIdx.x * ROWS_PER_BLOCK;

    // --- load per-row scalars (s2, v2) and bias ---
    if (tid < 256) {
        int r  = tid >> 2;
        int gr = min(row0 + r, n - 1);
        sc[tid] = in2[gr * 4 + (tid & 3)];
    }
    if (tid < 64) bsm[tid] = bias[tid];

    // --- load + interleave weights: Wp[u][w] = {Wss, Wvv, Wsv, Wvs} ---
    for (int idx = tid; idx < 4096; idx += THREADS) {
        Wp[idx * 4 + 0] = Wss[idx];
        Wp[idx * 4 + 1] = Wvv[idx];
        Wp[idx * 4 + 2] = Wsv[idx];
        Wp[idx * 4 + 3] = Wvs[idx];
    }
    __syncthreads();   // sc must be visible for A-pack below

    // --- pack per-row inputs: A[r][u] = {s1*s2, vv*inv_sqrt3, s1, v1x, v1y, v1z, -, -} ---
    for (int idx = tid; idx < 64 * 64; idx += THREADS) {
        int r  = idx >> 6;
        int u  = idx & 63;
        int gr = min(row0 + r, n - 1);
        const float* rowp = in1 + (long)gr * 256;
        float s1 = rowp[u];
        float vx = rowp[64 + 3 * u + 0];
        float vy = rowp[64 + 3 * u + 1];
        float vz = rowp[64 + 3 * u + 2];
        float s2  = sc[r * 4 + 0];
        float v2x = sc[r * 4 + 1];
        float v2y = sc[r * 4 + 2];
        float v2z = sc[r * 4 + 3];
        float vvs = (vx * v2x + vy * v2y + vz * v2z) * INV_SQRT3;
        float* ap = A + idx * 8;
        ap[0] = s1 * s2;
        ap[1] = vvs;
        ap[2] = s1;
        ap[3] = vx;
        ap[4] = vy;
        ap[5] = vz;
        ap[6] = 0.f;
        ap[7] = 0.f;
    }
    __syncthreads();

    // --- main u-loop: thread = 4 rows x 2 cols, 5 accumulators each ---
    const int c  = tid & 31;   // cols c, c+32  -> warp lanes cover 32 consecutive cols
    const int rg = tid >> 5;   // row group: rows 4*rg .. 4*rg+3 (uniform per warp -> broadcast A loads)

    float acc[4][2][5];
    #pragma unroll
    for (int r = 0; r < 4; r++)
        #pragma unroll
        for (int j = 0; j < 2; j++)
            #pragma unroll
            for (int k = 0; k < 5; k++) acc[r][j][k] = 0.f;

    const float4* A4 = (const float4*)A;
    const float4* W4 = (const float4*)Wp;

    #pragma unroll 4
    for (int u = 0; u < 64; u++) {
        float4 b0 = W4[u * 64 + c];        // {Wss,Wvv,Wsv,Wvs} for col c
        float4 b1 = W4[u * 64 + c + 32];   // for col c+32
        #pragma unroll
        for (int r = 0; r < 4; r++) {
            int base  = ((rg * 4 + r) * 64 + u) * 2;
            float4 a0 = A4[base];       // s1p, vvs, s1, v1x
            float4 a1 = A4[base + 1];   // v1y, v1z, -, -
            acc[r][0][0] += a0.x * b0.x;
            acc[r][0][0] += a0.y * b0.y;
            acc[r][0][1] += a0.z * b0.z;
            acc[r][0][2] += a0.w * b0.w;
            acc[r][0][3] += a1.x * b0.w;
            acc[r][0][4] += a1.y * b0.w;
            acc[r][1][0] += a0.x * b1.x;
            acc[r][1][0] += a0.y * b1.y;
            acc[r][1][1] += a0.z * b1.z;
            acc[r][1][2] += a0.w * b1.w;
            acc[r][1][3] += a1.x * b1.w;
            acc[r][1][4] += a1.y * b1.w;
        }
    }

    __syncthreads();   // all warps done reading A -> reuse it as output staging

    // --- epilogue: combine and stage into smem [64 rows][256 cols] ---
    float* stile = smem;
    #pragma unroll
    for (int r = 0; r < 4; r++) {
        int lr = rg * 4 + r;
        float s2  = sc[lr * 4 + 0];
        float v2x = sc[lr * 4 + 1];
        float v2y = sc[lr * 4 + 2];
        float v2z = sc[lr * 4 + 3];
        float* o = stile + lr * 256;
        #pragma unroll
        for (int j = 0; j < 2; j++) {
            int w = c + 32 * j;
            o[w] = acc[r][j][0] + bsm[w];
            float sv = acc[r][j][1];
            o[64 + 3 * w + 0] = sv * v2x + acc[r][j][2] * s2;
            o[64 + 3 * w + 1] = sv * v2y + acc[r][j][3] * s2;
            o[64 + 3 * w + 2] = sv * v2z + acc[r][j][4] * s2;
        }
    }
    __syncthreads();

    // --- coalesced float4 store of the whole tile ---
    const float4* st4 = (const float4*)stile;
    float4* out4 = (float4*)(out + (long)row0 * 256);
    int rows_here = min(ROWS_PER_BLOCK, n - row0);
    int nfl4 = rows_here * 64;   // 256 floats/row = 64 float4/row
    for (int idx = tid; idx < nfl4; idx += THREADS)
        out4[idx] = st4[idx];
}

extern "C" void kernel_launch(void* const* d_in, const int* in_sizes, int n_in,
                              void* d_out, int out_size) {
    const float* in1  = (const float*)d_in[0];
    const float* in2  = (const float*)d_in[1];
    const float* Wss  = (const float*)d_in[2];
    const float* Wvv  = (const float*)d_in[3];
    const float* Wsv  = (const float*)d_in[4];
    const float* Wvs  = (const float*)d_in[5];
    const float* bias = (const float*)d_in[6];
    float* out = (float*)d_out;

    int n = in_sizes[0] / 256;   // rows

    cudaFuncSetAttribute(o3tp_kernel, cudaFuncAttributeMaxDynamicSharedMemorySize, SMEM_BYTES);

    int blocks = (n + ROWS_PER_BLOCK - 1) / ROWS_PER_BLOCK;
    o3tp_kernel<<<blocks, THREADS, SMEM_BYTES>>>(in1, in2, Wss, Wvv, Wsv, Wvs, bias, out, n);
}